// round 10
// baseline (speedup 1.0000x reference)
#include <cuda_runtime.h>
#include <cuda_bf16.h>
#include <math.h>

// Problem dims (fixed per reference)
#define BATCH 4
#define SEQ   2048
#define DMODEL 1024
#define DK    128
#define MTOT  (BATCH*SEQ)   // 8192
#define NEG_BIG (-1e30f)

// ---------------- scratch (device globals; no allocation allowed) -----------
// g_Q, g_K stored k-PERMUTED within 8-groups: pos(k) = (k&3)*2 + (k>>2).
// g_V normal. g_O stored column-PERMUTED (same rule) for out_gemm A-frags.
__device__ float g_Q[MTOT * DK];
__device__ float g_K[MTOT * DK];
__device__ float g_V[MTOT * DK];
__device__ float g_O[MTOT * DK];

// split-KV partials: [B][32 q-tiles][8 chunks][64 rows][128 cols]
__device__ float g_pO[BATCH * 32 * 8 * 64 * 128];
__device__ float g_pm[BATCH * 32 * 8 * 64];
__device__ float g_pl[BATCH * 32 * 8 * 64];

// ---------------- tf32 helpers ------------------------------------------------
__device__ __forceinline__ unsigned f2tf(float x) {
    unsigned r;
    asm("cvt.rna.tf32.f32 %0, %1;" : "=r"(r) : "f"(x));
    return r;
}
__device__ __forceinline__ float f2tf_f(float x) { return __uint_as_float(f2tf(x)); }

// D = A(16x8, row) * B(8x8, col) + D, tf32 inputs, fp32 accum.
__device__ __forceinline__ void mma8(float* c, const unsigned* a, unsigned b0, unsigned b1) {
    asm volatile(
        "mma.sync.aligned.m16n8k8.row.col.f32.tf32.tf32.f32 "
        "{%0,%1,%2,%3},{%4,%5,%6,%7},{%8,%9},{%0,%1,%2,%3};"
        : "+f"(c[0]), "+f"(c[1]), "+f"(c[2]), "+f"(c[3])
        : "r"(a[0]), "r"(a[1]), "r"(a[2]), "r"(a[3]), "r"(b0), "r"(b1));
}

// ---------------- tf32 MMA GEMM body ------------------------------------------
// C[M,N] = A[M,K]*B[K,N] row-major. BM=64, BN=128, BK=16, 256 threads (8 warps).
// Warp grid 4(m) x 2(n); warp tile m16 x n64.
// As stored k-PERMUTED (A_LD=24): A-frags are single LDS.64 per row.
#define G_BM 64
#define G_BN 128
#define G_BK 16
#define A_LD 24
#define B_LD 136

#define EPI_PLAIN     0   // fp32, normal layout (final output)
#define EPI_TF32_PERM 1   // tf32-rounded, column-permuted (g_Q, g_K)
#define EPI_TF32      2   // tf32-rounded, normal (g_V)

template<bool APERM_IN>
__device__ __forceinline__ void mma_gemm(
    const float* __restrict__ A, const float* __restrict__ B, float* __restrict__ C,
    int N, int K, int m0, int n0, int epi,
    float (*As)[G_BM][A_LD], float (*Bs)[G_BK][B_LD])
{
    const int tid  = threadIdx.x;
    const int lane = tid & 31, wid = tid >> 5;
    const int gid  = lane >> 2, tg = lane & 3;
    const int wm   = (wid & 3) * 16;
    const int wn   = (wid >> 2) * 64;

    const int ar = tid >> 2, ac = (tid & 3) << 2;        // A tile: 64x16
    const int g8 = ac & 8, half = (ac >> 2) & 1;         // permute helpers
    const int br = tid >> 5, bc = (tid & 31) << 2;       // B tile: 16x128

    const float* Ap  = A + (size_t)(m0 + ar) * K + ac;
    const float* Bp0 = B + (size_t)br * N + n0 + bc;
    const float* Bp1 = B + (size_t)(br + 8) * N + n0 + bc;

    float acc[8][4];
#pragma unroll
    for (int nb = 0; nb < 8; ++nb)
#pragma unroll
        for (int j = 0; j < 4; ++j) acc[nb][j] = 0.f;

    // preload tile 0
    {
        float4 a  = *(const float4*)Ap;
        float4 b0 = *(const float4*)Bp0;
        float4 b1 = *(const float4*)Bp1;
        if (APERM_IN) {
            // A already permuted in gmem: straight (rounded) vector store
            float4 t = make_float4(f2tf_f(a.x), f2tf_f(a.y), f2tf_f(a.z), f2tf_f(a.w));
            *(float4*)&As[0][ar][ac] = t;
        } else {
            As[0][ar][g8 + half + 0] = f2tf_f(a.x);
            As[0][ar][g8 + half + 2] = f2tf_f(a.y);
            As[0][ar][g8 + half + 4] = f2tf_f(a.z);
            As[0][ar][g8 + half + 6] = f2tf_f(a.w);
        }
        Bs[0][br][bc+0]   = f2tf_f(b0.x); Bs[0][br][bc+1]   = f2tf_f(b0.y);
        Bs[0][br][bc+2]   = f2tf_f(b0.z); Bs[0][br][bc+3]   = f2tf_f(b0.w);
        Bs[0][br+8][bc+0] = f2tf_f(b1.x); Bs[0][br+8][bc+1] = f2tf_f(b1.y);
        Bs[0][br+8][bc+2] = f2tf_f(b1.z); Bs[0][br+8][bc+3] = f2tf_f(b1.w);
    }
    __syncthreads();

    const int nk = K / G_BK;
    for (int it = 0; it < nk; ++it) {
        const int buf = it & 1;
        const bool hn = (it + 1 < nk);
        float4 an, bn0, bn1;
        if (hn) {
            an  = *(const float4*)(Ap + (it + 1) * G_BK);
            bn0 = *(const float4*)(Bp0 + (size_t)(it + 1) * G_BK * N);
            bn1 = *(const float4*)(Bp1 + (size_t)(it + 1) * G_BK * N);
        }
#pragma unroll
        for (int kc = 0; kc < 2; ++kc) {
            float2 f0 = *(float2*)&As[buf][wm + gid    ][kc*8 + 2*tg];
            float2 f1 = *(float2*)&As[buf][wm + gid + 8][kc*8 + 2*tg];
            unsigned a[4] = { __float_as_uint(f0.x), __float_as_uint(f1.x),
                              __float_as_uint(f0.y), __float_as_uint(f1.y) };
#pragma unroll
            for (int nb = 0; nb < 8; ++nb) {
                unsigned b0 = __float_as_uint(Bs[buf][kc*8 + tg    ][wn + nb*8 + gid]);
                unsigned b1 = __float_as_uint(Bs[buf][kc*8 + tg + 4][wn + nb*8 + gid]);
                mma8(acc[nb], a, b0, b1);
            }
        }
        if (hn) {
            const int nxt = buf ^ 1;
            if (APERM_IN) {
                float4 t = make_float4(f2tf_f(an.x), f2tf_f(an.y), f2tf_f(an.z), f2tf_f(an.w));
                *(float4*)&As[nxt][ar][ac] = t;
            } else {
                As[nxt][ar][g8 + half + 0] = f2tf_f(an.x);
                As[nxt][ar][g8 + half + 2] = f2tf_f(an.y);
                As[nxt][ar][g8 + half + 4] = f2tf_f(an.z);
                As[nxt][ar][g8 + half + 6] = f2tf_f(an.w);
            }
            Bs[nxt][br][bc+0]   = f2tf_f(bn0.x); Bs[nxt][br][bc+1]   = f2tf_f(bn0.y);
            Bs[nxt][br][bc+2]   = f2tf_f(bn0.z); Bs[nxt][br][bc+3]   = f2tf_f(bn0.w);
            Bs[nxt][br+8][bc+0] = f2tf_f(bn1.x); Bs[nxt][br+8][bc+1] = f2tf_f(bn1.y);
            Bs[nxt][br+8][bc+2] = f2tf_f(bn1.z); Bs[nxt][br+8][bc+3] = f2tf_f(bn1.w);
            __syncthreads();
        }
    }

    // epilogue: C frag rows {wm+gid, wm+gid+8}, cols {wn+nb*8+2tg, +1}
    const int row = m0 + wm + gid;
#pragma unroll
    for (int nb = 0; nb < 8; ++nb) {
        const int colbase = n0 + wn + nb*8;
        if (epi == EPI_TF32_PERM) {
            // permuted positions of cols (2tg, 2tg+1)
            const int p0 = ((2*tg) & 3) * 2 + (tg >> 1);        // perm(2tg)
            const int p1 = ((2*tg+1) & 3) * 2 + ((2*tg+1) >> 2); // perm(2tg+1)
            C[(size_t)row * N + colbase + p0]       = f2tf_f(acc[nb][0]);
            C[(size_t)row * N + colbase + p1]       = f2tf_f(acc[nb][1]);
            C[(size_t)(row + 8) * N + colbase + p0] = f2tf_f(acc[nb][2]);
            C[(size_t)(row + 8) * N + colbase + p1] = f2tf_f(acc[nb][3]);
        } else if (epi == EPI_TF32) {
            const int col = colbase + 2*tg;
            *(float2*)&C[(size_t)row * N + col]       = make_float2(f2tf_f(acc[nb][0]), f2tf_f(acc[nb][1]));
            *(float2*)&C[(size_t)(row + 8) * N + col] = make_float2(f2tf_f(acc[nb][2]), f2tf_f(acc[nb][3]));
        } else {
            const int col = colbase + 2*tg;
            *(float2*)&C[(size_t)row * N + col]       = make_float2(acc[nb][0], acc[nb][1]);
            *(float2*)&C[(size_t)(row + 8) * N + col] = make_float2(acc[nb][2], acc[nb][3]);
        }
    }
}

// QKV projection: grid (1, M/64, 3). Q/K written permuted, V normal (all tf32-rounded).
__global__ __launch_bounds__(256) void qkv_gemm_kernel(
    const float* __restrict__ x,
    const float* __restrict__ Wq,
    const float* __restrict__ Wk,
    const float* __restrict__ Wv)
{
    __shared__ __align__(16) float As[2][G_BM][A_LD];
    __shared__ __align__(16) float Bs[2][G_BK][B_LD];
    const float* W; float* out; int epi;
    if (blockIdx.z == 0)      { W = Wq; out = g_Q; epi = EPI_TF32_PERM; }
    else if (blockIdx.z == 1) { W = Wk; out = g_K; epi = EPI_TF32_PERM; }
    else                      { W = Wv; out = g_V; epi = EPI_TF32; }
    mma_gemm<false>(x, W, out, DK, DMODEL, blockIdx.y * G_BM, 0, epi, As, Bs);
}

// Output projection: grid (DMODEL/128, M/64). A (= g_O) is pre-permuted by merge.
__global__ __launch_bounds__(256) void out_gemm_kernel(
    const float* __restrict__ Wo, float* __restrict__ out)
{
    __shared__ __align__(16) float As[2][G_BM][A_LD];
    __shared__ __align__(16) float Bs[2][G_BK][B_LD];
    mma_gemm<true>(g_O, Wo, out, DMODEL, DK, blockIdx.y * G_BM, blockIdx.x * G_BN,
                   EPI_PLAIN, As, Bs);
}

// ---------------- flash attention phase 1: split-KV, tf32 mma -----------------
// BQ=64, BKV=32, DH=128. 128 threads = 4 warps; warp w owns q-rows [16w,16w+16).
// Q resident in smem (permuted, from permuted g_Q); K permuted; V normal.
// KV chunks of 8 kv32-tiles (256 keys). Blocks/batch = sum_qi (qi/4+1) = 144.
#define BKV 32
#define LDQ 132
#define LDK 132
#define LDV 132
#define LDP 34
#define ATT_SMEM ((64*LDQ + BKV*LDK + BKV*LDV + 64*LDP) * sizeof(float))

__global__ __launch_bounds__(128, 3) void attn_partial_kernel()
{
    extern __shared__ float sm[];
    float* Qs = sm;                   // 64 x 132 (permuted k)
    float* Ks = Qs + 64 * LDQ;        // 32 x 132 (permuted k)
    float* Vs = Ks + BKV * LDK;       // 32 x 132 (normal)
    float* Ps = Vs + BKV * LDV;       // 64 x 34

    const int tid  = threadIdx.x;
    const int lane = tid & 31, wid = tid >> 5;
    const int gid  = lane >> 2, tg = lane & 3;
    const int b    = blockIdx.y;

    // decode (qi, ch): qi-group g (qi in [4g,4g+4)) has g+1 chunks per q-tile
    int i = blockIdx.x, g = 0;
    while (i >= 4 * (g + 1)) { i -= 4 * (g + 1); ++g; }
    const int qi = 4 * g + i / (g + 1);
    const int ch = i - (i / (g + 1)) * (g + 1);
    const int q0 = qi * 64;
    const int kt_begin = ch * 8;                    // in 32-key tiles
    const int kt_end   = min(ch * 8 + 8, 2 * qi + 2);

    const float* Qg = g_Q + (size_t)b * SEQ * DK;
    const float* Kg = g_K + (size_t)b * SEQ * DK;
    const float* Vg = g_V + (size_t)b * SEQ * DK;

    const int r0 = wid * 16 + gid;   // warp A-fragment base row

    // load Q tile (already tf32-rounded + permuted in gmem): plain vector copy
#pragma unroll
    for (int t = 0; t < 16; ++t) {
        int e = t * 128 + tid;                 // float4 index, 0..2047
        int row = e >> 5, c4 = (e & 31) << 2;
        *(float4*)&Qs[row * LDQ + c4] = *(const float4*)&Qg[(size_t)(q0 + row) * DK + c4];
    }

    float ob[16][4];
#pragma unroll
    for (int nb = 0; nb < 16; ++nb)
#pragma unroll
        for (int j = 0; j < 4; ++j) ob[nb][j] = 0.f;
    float m[2] = {NEG_BIG, NEG_BIG}, l[2] = {0.f, 0.f};
    const float scale = 0.08838834764831845f;  // 1/sqrt(128)

    for (int kt = kt_begin; kt < kt_end; ++kt) {
        const int k0 = kt * BKV;
        const bool diag = (k0 + BKV > q0);

        __syncthreads();   // all warps done reading Ks/Vs from previous tile
#pragma unroll
        for (int t = 0; t < 8; ++t) {
            int e = t * 128 + tid;             // float4 index, 0..1023
            int row = e >> 5, c4 = (e & 31) << 2;
            *(float4*)&Ks[row * LDK + c4] = *(const float4*)&Kg[(size_t)(k0 + row) * DK + c4];
            *(float4*)&Vs[row * LDV + c4] = *(const float4*)&Vg[(size_t)(k0 + row) * DK + c4];
        }
        __syncthreads();

        // S = Q K^T  (warp: m16 x n32, k=128); frags via LDS.64 from permuted layout
        float sc[4][4];
#pragma unroll
        for (int nb = 0; nb < 4; ++nb)
#pragma unroll
            for (int j = 0; j < 4; ++j) sc[nb][j] = 0.f;

#pragma unroll
        for (int kc = 0; kc < 16; ++kc) {
            float2 q0f = *(float2*)&Qs[(r0    ) * LDQ + kc*8 + 2*tg];
            float2 q1f = *(float2*)&Qs[(r0 + 8) * LDQ + kc*8 + 2*tg];
            unsigned qa[4] = { __float_as_uint(q0f.x), __float_as_uint(q1f.x),
                               __float_as_uint(q0f.y), __float_as_uint(q1f.y) };
#pragma unroll
            for (int nb = 0; nb < 4; ++nb) {
                float2 bf = *(float2*)&Ks[(nb*8 + gid) * LDK + kc*8 + 2*tg];
                mma8(sc[nb], qa, __float_as_uint(bf.x), __float_as_uint(bf.y));
            }
        }

        // fragment-resident softmax (rows: r0 for c{0,1}, r0+8 for c{2,3})
#pragma unroll
        for (int r = 0; r < 2; ++r) {
            const int qg = q0 + r0 + r*8;
            float mx = NEG_BIG;
#pragma unroll
            for (int nb = 0; nb < 4; ++nb) {
#pragma unroll
                for (int j = 0; j < 2; ++j) {
                    float v = sc[nb][2*r + j] * scale;
                    if (diag) {
                        const int kg = k0 + nb*8 + 2*tg + j;
                        if (kg > qg) v = NEG_BIG;
                    }
                    sc[nb][2*r + j] = v;
                    mx = fmaxf(mx, v);
                }
            }
            mx = fmaxf(mx, __shfl_xor_sync(0xffffffffu, mx, 1));
            mx = fmaxf(mx, __shfl_xor_sync(0xffffffffu, mx, 2));
            const float mnew  = fmaxf(m[r], mx);
            const float alpha = __expf(m[r] - mnew);
            float sum = 0.f;
#pragma unroll
            for (int nb = 0; nb < 4; ++nb) {
                float p0 = __expf(sc[nb][2*r    ] - mnew);
                float p1 = __expf(sc[nb][2*r + 1] - mnew);
                sum += p0 + p1;
                *(float2*)&Ps[(r0 + r*8) * LDP + nb*8 + 2*tg] = make_float2(f2tf_f(p0), f2tf_f(p1));
            }
            sum += __shfl_xor_sync(0xffffffffu, sum, 1);
            sum += __shfl_xor_sync(0xffffffffu, sum, 2);
            l[r] = l[r] * alpha + sum;
            m[r] = mnew;
#pragma unroll
            for (int nb = 0; nb < 16; ++nb) {
                ob[nb][2*r    ] *= alpha;
                ob[nb][2*r + 1] *= alpha;
            }
        }
        __syncwarp();   // Ps rows are warp-private: warp-level visibility suffices

        // O += P * V  (warp: m16 x n128, k=32)
#pragma unroll
        for (int kc = 0; kc < 4; ++kc) {
            unsigned pa[4];
            pa[0] = __float_as_uint(Ps[(r0    ) * LDP + kc*8 + tg    ]);
            pa[1] = __float_as_uint(Ps[(r0 + 8) * LDP + kc*8 + tg    ]);
            pa[2] = __float_as_uint(Ps[(r0    ) * LDP + kc*8 + tg + 4]);
            pa[3] = __float_as_uint(Ps[(r0 + 8) * LDP + kc*8 + tg + 4]);
#pragma unroll
            for (int nb = 0; nb < 16; ++nb) {
                unsigned b0 = __float_as_uint(Vs[(kc*8 + tg    ) * LDV + nb*8 + gid]);
                unsigned b1 = __float_as_uint(Vs[(kc*8 + tg + 4) * LDV + nb*8 + gid]);
                mma8(ob[nb], pa, b0, b1);
            }
        }
    }

    // store UNNORMALIZED partial O + per-row (m, l)   (normal layout)
    const int slot = (b * 32 + qi) * 8 + ch;
    float* pO = g_pO + (size_t)slot * (64 * 128);
#pragma unroll
    for (int nb = 0; nb < 16; ++nb) {
        const int col = nb*8 + 2*tg;
        *(float2*)&pO[(size_t)(r0    ) * 128 + col] = make_float2(ob[nb][0], ob[nb][1]);
        *(float2*)&pO[(size_t)(r0 + 8) * 128 + col] = make_float2(ob[nb][2], ob[nb][3]);
    }
    if (tg == 0) {
        g_pm[slot * 64 + r0]     = m[0];
        g_pl[slot * 64 + r0]     = l[0];
        g_pm[slot * 64 + r0 + 8] = m[1];
        g_pl[slot * 64 + r0 + 8] = l[1];
    }
}

// ---------------- flash attention phase 2: merge partials ---------------------
// grid (32, 4), 256 threads. Writes g_O column-PERMUTED for out_gemm A-frags.
__global__ __launch_bounds__(256) void attn_merge_kernel()
{
    const int qi = blockIdx.x;
    const int b  = blockIdx.y;
    const int nc = (qi >> 2) + 1;          // up to 8 chunks of 256 keys
    const int tid = threadIdx.x;
    const int r  = tid >> 2;
    const int cg = (tid & 3) << 5;
    const int base = (b * 32 + qi) * 8;

    float mc[8], wc[8];
    float mstar = NEG_BIG;
    for (int c = 0; c < nc; ++c) {
        mc[c] = g_pm[(base + c) * 64 + r];
        mstar = fmaxf(mstar, mc[c]);
    }
    float L = 0.f;
    for (int c = 0; c < nc; ++c) {
        wc[c] = __expf(mc[c] - mstar);
        L += wc[c] * g_pl[(base + c) * 64 + r];
    }
    const float inv = 1.f / L;

    float acc[32];
#pragma unroll
    for (int j = 0; j < 32; ++j) acc[j] = 0.f;

    for (int c = 0; c < nc; ++c) {
        const float w = wc[c];
        const float* src = g_pO + (size_t)(base + c) * (64 * 128) + (size_t)r * 128 + cg;
#pragma unroll
        for (int v = 0; v < 8; ++v) {
            float4 t = *(const float4*)&src[v * 4];
            acc[v*4+0] = fmaf(w, t.x, acc[v*4+0]);
            acc[v*4+1] = fmaf(w, t.y, acc[v*4+1]);
            acc[v*4+2] = fmaf(w, t.z, acc[v*4+2]);
            acc[v*4+3] = fmaf(w, t.w, acc[v*4+3]);
        }
    }

    // permuted store: col c = cg + v*4 + j -> group + 2j + (v&1)
    float* dst = g_O + (size_t)b * SEQ * DK + (size_t)(qi * 64 + r) * 128;
#pragma unroll
    for (int v = 0; v < 8; ++v) {
        const int gbase = cg + (v >> 1) * 8;
        const int off   = v & 1;
#pragma unroll
        for (int j = 0; j < 4; ++j)
            dst[gbase + 2*j + off] = acc[v*4 + j] * inv;
    }
}

// ---------------- launch ------------------------------------------------------
extern "C" void kernel_launch(void* const* d_in, const int* in_sizes, int n_in,
                              void* d_out, int out_size)
{
    const float* x  = (const float*)d_in[0];
    const float* Wq = (const float*)d_in[1];
    const float* Wk = (const float*)d_in[2];
    const float* Wv = (const float*)d_in[3];
    const float* Wo = (const float*)d_in[4];
    float* out = (float*)d_out;

    cudaFuncSetAttribute(attn_partial_kernel,
                         cudaFuncAttributeMaxDynamicSharedMemorySize, (int)ATT_SMEM);

    // 1) QKV projections (tf32 mma): M=8192, N=128, K=1024
    {
        dim3 grid(1, MTOT / G_BM, 3);
        qkv_gemm_kernel<<<grid, 256>>>(x, Wq, Wk, Wv);
    }
    // 2a) causal flash attention, split-KV partials (144 blocks/batch)
    {
        dim3 grid(144, BATCH);
        attn_partial_kernel<<<grid, 128, ATT_SMEM>>>();
    }
    // 2b) merge partials (writes permuted g_O)
    {
        dim3 grid(32, BATCH);
        attn_merge_kernel<<<grid, 256>>>();
    }
    // 3) output projection (tf32 mma): M=8192, N=1024, K=128
    {
        dim3 grid(DMODEL / G_BN, MTOT / G_BM);
        out_gemm_kernel<<<grid, 256>>>(Wo, out);
    }
}

// round 11
// speedup vs baseline: 1.2414x; 1.2414x over previous
#include <cuda_runtime.h>
#include <cuda_bf16.h>
#include <math.h>

// Problem dims (fixed per reference)
#define BATCH 4
#define SEQ   2048
#define DMODEL 1024
#define DK    128
#define MTOT  (BATCH*SEQ)   // 8192
#define NEG_BIG (-1e30f)

// ---------------- scratch (device globals; no allocation allowed) -----------
// g_Q, g_K stored k-PERMUTED within 8-groups: pos(c) = (c&3)*2 + (c>>2)
// (so fragment pairs {c, c+4} are adjacent -> LDS.64/LDG.64 fragment loads).
// g_V, g_O normal layout.
__device__ float g_Q[MTOT * DK];
__device__ float g_K[MTOT * DK];
__device__ float g_V[MTOT * DK];
__device__ float g_O[MTOT * DK];

// split-KV partials: [B][32 q-tiles][4 chunks][64 rows][128 cols]
__device__ float g_pO[BATCH * 32 * 4 * 64 * 128];
__device__ float g_pm[BATCH * 32 * 4 * 64];
__device__ float g_pl[BATCH * 32 * 4 * 64];

// ---------------- tf32 helpers ------------------------------------------------
__device__ __forceinline__ unsigned f2tf(float x) {
    unsigned r;
    asm("cvt.rna.tf32.f32 %0, %1;" : "=r"(r) : "f"(x));
    return r;
}
__device__ __forceinline__ float f2tf_f(float x) { return __uint_as_float(f2tf(x)); }

// D = A(16x8, row) * B(8x8, col) + D, tf32 inputs, fp32 accum.
__device__ __forceinline__ void mma8(float* c, const unsigned* a, unsigned b0, unsigned b1) {
    asm volatile(
        "mma.sync.aligned.m16n8k8.row.col.f32.tf32.tf32.f32 "
        "{%0,%1,%2,%3},{%4,%5,%6,%7},{%8,%9},{%0,%1,%2,%3};"
        : "+f"(c[0]), "+f"(c[1]), "+f"(c[2]), "+f"(c[3])
        : "r"(a[0]), "r"(a[1]), "r"(a[2]), "r"(a[3]), "r"(b0), "r"(b1));
}

// ---------------- tf32 MMA GEMM body ------------------------------------------
// C[M,N] = A[M,K]*B[K,N] row-major. BM=64, BN=128, BK=16, 256 threads (8 warps).
// Warp grid 4(m) x 2(n); warp tile m16 x n64.
// As stored k-PERMUTED (A_LD=24): A-frags are single LDS.64 per row.
#define G_BM 64
#define G_BN 128
#define G_BK 16
#define A_LD 24
#define B_LD 136

#define EPI_PLAIN     0   // fp32, normal layout (final output)
#define EPI_TF32_PERM 1   // tf32-rounded, column-permuted (g_Q, g_K)
#define EPI_TF32      2   // tf32-rounded, normal (g_V)

__device__ __forceinline__ void mma_gemm(
    const float* __restrict__ A, const float* __restrict__ B, float* __restrict__ C,
    int N, int K, int m0, int n0, int epi,
    float (*As)[G_BM][A_LD], float (*Bs)[G_BK][B_LD])
{
    const int tid  = threadIdx.x;
    const int lane = tid & 31, wid = tid >> 5;
    const int gid  = lane >> 2, tg = lane & 3;
    const int wm   = (wid & 3) * 16;
    const int wn   = (wid >> 2) * 64;

    const int ar = tid >> 2, ac = (tid & 3) << 2;        // A tile: 64x16
    const int g8 = ac & 8, half = (ac >> 2) & 1;         // permute helpers
    const int br = tid >> 5, bc = (tid & 31) << 2;       // B tile: 16x128

    const float* Ap  = A + (size_t)(m0 + ar) * K + ac;
    const float* Bp0 = B + (size_t)br * N + n0 + bc;
    const float* Bp1 = B + (size_t)(br + 8) * N + n0 + bc;

    float acc[8][4];
#pragma unroll
    for (int nb = 0; nb < 8; ++nb)
#pragma unroll
        for (int j = 0; j < 4; ++j) acc[nb][j] = 0.f;

    // preload tile 0 (A stored permuted into smem)
    {
        float4 a  = *(const float4*)Ap;
        float4 b0 = *(const float4*)Bp0;
        float4 b1 = *(const float4*)Bp1;
        As[0][ar][g8 + half + 0] = f2tf_f(a.x);
        As[0][ar][g8 + half + 2] = f2tf_f(a.y);
        As[0][ar][g8 + half + 4] = f2tf_f(a.z);
        As[0][ar][g8 + half + 6] = f2tf_f(a.w);
        Bs[0][br][bc+0]   = f2tf_f(b0.x); Bs[0][br][bc+1]   = f2tf_f(b0.y);
        Bs[0][br][bc+2]   = f2tf_f(b0.z); Bs[0][br][bc+3]   = f2tf_f(b0.w);
        Bs[0][br+8][bc+0] = f2tf_f(b1.x); Bs[0][br+8][bc+1] = f2tf_f(b1.y);
        Bs[0][br+8][bc+2] = f2tf_f(b1.z); Bs[0][br+8][bc+3] = f2tf_f(b1.w);
    }
    __syncthreads();

    const int nk = K / G_BK;
    for (int it = 0; it < nk; ++it) {
        const int buf = it & 1;
        const bool hn = (it + 1 < nk);
        float4 an, bn0, bn1;
        if (hn) {
            an  = *(const float4*)(Ap + (it + 1) * G_BK);
            bn0 = *(const float4*)(Bp0 + (size_t)(it + 1) * G_BK * N);
            bn1 = *(const float4*)(Bp1 + (size_t)(it + 1) * G_BK * N);
        }
#pragma unroll
        for (int kc = 0; kc < 2; ++kc) {
            float2 f0 = *(float2*)&As[buf][wm + gid    ][kc*8 + 2*tg];
            float2 f1 = *(float2*)&As[buf][wm + gid + 8][kc*8 + 2*tg];
            unsigned a[4] = { __float_as_uint(f0.x), __float_as_uint(f1.x),
                              __float_as_uint(f0.y), __float_as_uint(f1.y) };
#pragma unroll
            for (int nb = 0; nb < 8; ++nb) {
                unsigned b0 = __float_as_uint(Bs[buf][kc*8 + tg    ][wn + nb*8 + gid]);
                unsigned b1 = __float_as_uint(Bs[buf][kc*8 + tg + 4][wn + nb*8 + gid]);
                mma8(acc[nb], a, b0, b1);
            }
        }
        if (hn) {
            const int nxt = buf ^ 1;
            As[nxt][ar][g8 + half + 0] = f2tf_f(an.x);
            As[nxt][ar][g8 + half + 2] = f2tf_f(an.y);
            As[nxt][ar][g8 + half + 4] = f2tf_f(an.z);
            As[nxt][ar][g8 + half + 6] = f2tf_f(an.w);
            Bs[nxt][br][bc+0]   = f2tf_f(bn0.x); Bs[nxt][br][bc+1]   = f2tf_f(bn0.y);
            Bs[nxt][br][bc+2]   = f2tf_f(bn0.z); Bs[nxt][br][bc+3]   = f2tf_f(bn0.w);
            Bs[nxt][br+8][bc+0] = f2tf_f(bn1.x); Bs[nxt][br+8][bc+1] = f2tf_f(bn1.y);
            Bs[nxt][br+8][bc+2] = f2tf_f(bn1.z); Bs[nxt][br+8][bc+3] = f2tf_f(bn1.w);
            __syncthreads();
        }
    }

    // epilogue: C frag rows {wm+gid, wm+gid+8}, cols {wn+nb*8+2tg, +1}
    const int row = m0 + wm + gid;
#pragma unroll
    for (int nb = 0; nb < 8; ++nb) {
        const int colbase = n0 + wn + nb*8;
        if (epi == EPI_TF32_PERM) {
            const int p0 = ((2*tg) & 3) * 2 + (tg >> 1);          // perm(2tg)
            const int p1 = ((2*tg+1) & 3) * 2 + (tg >> 1);        // perm(2tg+1)
            C[(size_t)row * N + colbase + p0]       = f2tf_f(acc[nb][0]);
            C[(size_t)row * N + colbase + p1]       = f2tf_f(acc[nb][1]);
            C[(size_t)(row + 8) * N + colbase + p0] = f2tf_f(acc[nb][2]);
            C[(size_t)(row + 8) * N + colbase + p1] = f2tf_f(acc[nb][3]);
        } else if (epi == EPI_TF32) {
            const int col = colbase + 2*tg;
            *(float2*)&C[(size_t)row * N + col]       = make_float2(f2tf_f(acc[nb][0]), f2tf_f(acc[nb][1]));
            *(float2*)&C[(size_t)(row + 8) * N + col] = make_float2(f2tf_f(acc[nb][2]), f2tf_f(acc[nb][3]));
        } else {
            const int col = colbase + 2*tg;
            *(float2*)&C[(size_t)row * N + col]       = make_float2(acc[nb][0], acc[nb][1]);
            *(float2*)&C[(size_t)(row + 8) * N + col] = make_float2(acc[nb][2], acc[nb][3]);
        }
    }
}

// QKV projection: grid (1, M/64, 3). Q/K written permuted, V normal (tf32-rounded).
__global__ __launch_bounds__(256) void qkv_gemm_kernel(
    const float* __restrict__ x,
    const float* __restrict__ Wq,
    const float* __restrict__ Wk,
    const float* __restrict__ Wv)
{
    __shared__ __align__(16) float As[2][G_BM][A_LD];
    __shared__ __align__(16) float Bs[2][G_BK][B_LD];
    const float* W; float* out; int epi;
    if (blockIdx.z == 0)      { W = Wq; out = g_Q; epi = EPI_TF32_PERM; }
    else if (blockIdx.z == 1) { W = Wk; out = g_K; epi = EPI_TF32_PERM; }
    else                      { W = Wv; out = g_V; epi = EPI_TF32; }
    mma_gemm(x, W, out, DK, DMODEL, blockIdx.y * G_BM, 0, epi, As, Bs);
}

// Output projection: grid (DMODEL/128, M/64). A = g_O, normal layout.
__global__ __launch_bounds__(256) void out_gemm_kernel(
    const float* __restrict__ Wo, float* __restrict__ out)
{
    __shared__ __align__(16) float As[2][G_BM][A_LD];
    __shared__ __align__(16) float Bs[2][G_BK][B_LD];
    mma_gemm(g_O, Wo, out, DMODEL, DK, blockIdx.y * G_BM, blockIdx.x * G_BN,
             EPI_PLAIN, As, Bs);
}

// ---------------- flash attention phase 1: split-KV, tf32 mma -----------------
// BQ=64, BKV=64, DH=128. 128 threads = 4 warps; warp w owns q-rows [16w,16w+16).
// Q fragments register-resident (direct LDG.64 from permuted g_Q).
// K permuted in gmem -> S-phase B-frags are LDS.64. V normal.
// KV chunks of 8 kv64-tiles (512 keys). 80 blocks/batch (R9 schedule).
#define K_LD 136
#define PS_LD 72
#define ATT_SMEM ((2 * 64 * K_LD + 64 * PS_LD) * sizeof(float))

__global__ __launch_bounds__(128) void attn_partial_kernel()
{
    extern __shared__ float sm[];
    float* Ks = sm;                   // 64 x 136 (permuted k, straight copy of g_K)
    float* Vs = Ks + 64 * K_LD;       // 64 x 136 (normal)
    float* Ps = Vs + 64 * K_LD;       // 64 x 72

    const int tid  = threadIdx.x;
    const int lane = tid & 31, wid = tid >> 5;
    const int gid  = lane >> 2, tg = lane & 3;
    const int b    = blockIdx.y;

    // decode (q-tile, chunk) from flattened block index
    int qi, ch;
    {
        const int i = blockIdx.x;
        if (i < 8)       { qi = i;               ch = 0; }
        else if (i < 24) { int j = i - 8;  qi = 8  + (j >> 1); ch = j & 1; }
        else if (i < 48) { int j = i - 24; qi = 16 + j / 3;    ch = j - (j / 3) * 3; }
        else             { int j = i - 48; qi = 24 + (j >> 2); ch = j & 3; }
    }
    const int q0 = qi * 64;
    const int kt_begin = ch * 8;
    const int kt_end   = min(kt_begin + 8, qi + 1);

    const float* Qg = g_Q + (size_t)b * SEQ * DK;
    const float* Kg = g_K + (size_t)b * SEQ * DK;
    const float* Vg = g_V + (size_t)b * SEQ * DK;

    const int r0 = wid * 16 + gid;   // warp-local A-fragment base row

    // Q fragments: direct vector loads from permuted g_Q (no smem staging)
    unsigned qa[16][4];
#pragma unroll
    for (int kc = 0; kc < 16; ++kc) {
        float2 q0f = *(const float2*)&Qg[(size_t)(q0 + r0    ) * DK + kc*8 + 2*tg];
        float2 q1f = *(const float2*)&Qg[(size_t)(q0 + r0 + 8) * DK + kc*8 + 2*tg];
        qa[kc][0] = __float_as_uint(q0f.x);
        qa[kc][1] = __float_as_uint(q1f.x);
        qa[kc][2] = __float_as_uint(q0f.y);
        qa[kc][3] = __float_as_uint(q1f.y);
    }

    float ob[16][4];
#pragma unroll
    for (int nb = 0; nb < 16; ++nb)
#pragma unroll
        for (int j = 0; j < 4; ++j) ob[nb][j] = 0.f;
    float m[2] = {NEG_BIG, NEG_BIG}, l[2] = {0.f, 0.f};
    const float scale = 0.08838834764831845f;  // 1/sqrt(128)

    for (int kt = kt_begin; kt < kt_end; ++kt) {
        const int k0 = kt * 64;
        const bool diag = (kt == qi);

        if (kt > kt_begin) __syncthreads();  // all warps done with Ks/Vs/Ps of prev tile
        // load K (permuted, straight copy), V (normal) tiles
#pragma unroll
        for (int t = 0; t < 16; ++t) {
            int e = t * 128 + tid;             // float4 index, 0..2047
            int row = e >> 5, c4 = (e & 31) << 2;
            *(float4*)&Ks[row * K_LD + c4] = *(const float4*)&Kg[(size_t)(k0 + row) * DK + c4];
            *(float4*)&Vs[row * K_LD + c4] = *(const float4*)&Vg[(size_t)(k0 + row) * DK + c4];
        }
        __syncthreads();

        // S = Q K^T  (warp: m16 x n64, k=128); K B-frags = LDS.64 (permuted layout)
        float sc[8][4];
#pragma unroll
        for (int nb = 0; nb < 8; ++nb)
#pragma unroll
            for (int j = 0; j < 4; ++j) sc[nb][j] = 0.f;

#pragma unroll
        for (int kc = 0; kc < 16; ++kc) {
#pragma unroll
            for (int nb = 0; nb < 8; ++nb) {
                float2 bf = *(float2*)&Ks[(nb*8 + gid) * K_LD + kc*8 + 2*tg];
                mma8(sc[nb], qa[kc], __float_as_uint(bf.x), __float_as_uint(bf.y));
            }
        }

        // fragment-resident softmax (rows: r0 for c{0,1}, r0+8 for c{2,3})
#pragma unroll
        for (int r = 0; r < 2; ++r) {
            const int qg = q0 + r0 + r*8;
            float mx = NEG_BIG;
#pragma unroll
            for (int nb = 0; nb < 8; ++nb) {
#pragma unroll
                for (int j = 0; j < 2; ++j) {
                    float v = sc[nb][2*r + j] * scale;
                    if (diag) {
                        const int kg = k0 + nb*8 + 2*tg + j;
                        if (kg > qg) v = NEG_BIG;
                    }
                    sc[nb][2*r + j] = v;
                    mx = fmaxf(mx, v);
                }
            }
            mx = fmaxf(mx, __shfl_xor_sync(0xffffffffu, mx, 1));
            mx = fmaxf(mx, __shfl_xor_sync(0xffffffffu, mx, 2));
            const float mnew  = fmaxf(m[r], mx);
            const float alpha = __expf(m[r] - mnew);
            float sum = 0.f;
#pragma unroll
            for (int nb = 0; nb < 8; ++nb) {
                float p0 = __expf(sc[nb][2*r    ] - mnew);
                float p1 = __expf(sc[nb][2*r + 1] - mnew);
                sum += p0 + p1;
                *(float2*)&Ps[(r0 + r*8) * PS_LD + nb*8 + 2*tg] = make_float2(f2tf_f(p0), f2tf_f(p1));
            }
            sum += __shfl_xor_sync(0xffffffffu, sum, 1);
            sum += __shfl_xor_sync(0xffffffffu, sum, 2);
            l[r] = l[r] * alpha + sum;
            m[r] = mnew;
#pragma unroll
            for (int nb = 0; nb < 16; ++nb) {
                ob[nb][2*r    ] *= alpha;
                ob[nb][2*r + 1] *= alpha;
            }
        }
        __syncwarp();   // Ps rows are warp-private

        // O += P * V  (warp: m16 x n128, k=64)
#pragma unroll
        for (int kc = 0; kc < 8; ++kc) {
            unsigned pa[4];
            pa[0] = __float_as_uint(Ps[(r0    ) * PS_LD + kc*8 + tg    ]);
            pa[1] = __float_as_uint(Ps[(r0 + 8) * PS_LD + kc*8 + tg    ]);
            pa[2] = __float_as_uint(Ps[(r0    ) * PS_LD + kc*8 + tg + 4]);
            pa[3] = __float_as_uint(Ps[(r0 + 8) * PS_LD + kc*8 + tg + 4]);
#pragma unroll
            for (int nb = 0; nb < 16; ++nb) {
                unsigned b0 = __float_as_uint(Vs[(kc*8 + tg    ) * K_LD + nb*8 + gid]);
                unsigned b1 = __float_as_uint(Vs[(kc*8 + tg + 4) * K_LD + nb*8 + gid]);
                mma8(ob[nb], pa, b0, b1);
            }
        }
    }

    // store UNNORMALIZED partial O + per-row (m, l)   (normal layout)
    const int slot = (b * 32 + qi) * 4 + ch;
    float* pO = g_pO + (size_t)slot * (64 * 128);
#pragma unroll
    for (int nb = 0; nb < 16; ++nb) {
        const int col = nb*8 + 2*tg;
        *(float2*)&pO[(size_t)(r0    ) * 128 + col] = make_float2(ob[nb][0], ob[nb][1]);
        *(float2*)&pO[(size_t)(r0 + 8) * 128 + col] = make_float2(ob[nb][2], ob[nb][3]);
    }
    if (tg == 0) {
        g_pm[slot * 64 + r0]     = m[0];
        g_pl[slot * 64 + r0]     = l[0];
        g_pm[slot * 64 + r0 + 8] = m[1];
        g_pl[slot * 64 + r0 + 8] = l[1];
    }
}

// ---------------- flash attention phase 2: merge partials ---------------------
// grid (32, 4), 256 threads. Normal-layout g_O (float4 stores).
__global__ __launch_bounds__(256) void attn_merge_kernel()
{
    const int qi = blockIdx.x;
    const int b  = blockIdx.y;
    const int nc = (qi >> 3) + 1;
    const int tid = threadIdx.x;
    const int r  = tid >> 2;
    const int cg = (tid & 3) << 5;
    const int base = (b * 32 + qi) * 4;

    float mc[4], wc[4];
    float mstar = NEG_BIG;
    for (int c = 0; c < nc; ++c) {
        mc[c] = g_pm[(base + c) * 64 + r];
        mstar = fmaxf(mstar, mc[c]);
    }
    float L = 0.f;
    for (int c = 0; c < nc; ++c) {
        wc[c] = __expf(mc[c] - mstar);
        L += wc[c] * g_pl[(base + c) * 64 + r];
    }
    const float inv = 1.f / L;

    float acc[32];
#pragma unroll
    for (int j = 0; j < 32; ++j) acc[j] = 0.f;

    for (int c = 0; c < nc; ++c) {
        const float w = wc[c];
        const float* src = g_pO + (size_t)(base + c) * (64 * 128) + (size_t)r * 128 + cg;
#pragma unroll
        for (int v = 0; v < 8; ++v) {
            float4 t = *(const float4*)&src[v * 4];
            acc[v*4+0] = fmaf(w, t.x, acc[v*4+0]);
            acc[v*4+1] = fmaf(w, t.y, acc[v*4+1]);
            acc[v*4+2] = fmaf(w, t.z, acc[v*4+2]);
            acc[v*4+3] = fmaf(w, t.w, acc[v*4+3]);
        }
    }

    float* dst = g_O + (size_t)b * SEQ * DK + (size_t)(qi * 64 + r) * 128 + cg;
#pragma unroll
    for (int v = 0; v < 8; ++v) {
        float4 t = make_float4(acc[v*4+0]*inv, acc[v*4+1]*inv, acc[v*4+2]*inv, acc[v*4+3]*inv);
        *(float4*)&dst[v * 4] = t;
    }
}

// ---------------- launch ------------------------------------------------------
extern "C" void kernel_launch(void* const* d_in, const int* in_sizes, int n_in,
                              void* d_out, int out_size)
{
    const float* x  = (const float*)d_in[0];
    const float* Wq = (const float*)d_in[1];
    const float* Wk = (const float*)d_in[2];
    const float* Wv = (const float*)d_in[3];
    const float* Wo = (const float*)d_in[4];
    float* out = (float*)d_out;

    cudaFuncSetAttribute(attn_partial_kernel,
                         cudaFuncAttributeMaxDynamicSharedMemorySize, (int)ATT_SMEM);

    // 1) QKV projections (tf32 mma): M=8192, N=128, K=1024
    {
        dim3 grid(1, MTOT / G_BM, 3);
        qkv_gemm_kernel<<<grid, 256>>>(x, Wq, Wk, Wv);
    }
    // 2a) causal flash attention, split-KV partials (80 blocks/batch)
    {
        dim3 grid(80, BATCH);
        attn_partial_kernel<<<grid, 128, ATT_SMEM>>>();
    }
    // 2b) merge partials
    {
        dim3 grid(32, BATCH);
        attn_merge_kernel<<<grid, 256>>>();
    }
    // 3) output projection (tf32 mma): M=8192, N=1024, K=128
    {
        dim3 grid(DMODEL / G_BN, MTOT / G_BM);
        out_gemm_kernel<<<grid, 256>>>(Wo, out);
    }
}

// round 14
// speedup vs baseline: 1.2441x; 1.0022x over previous
#include <cuda_runtime.h>
#include <cuda_bf16.h>
#include <math.h>

// Problem dims (fixed per reference)
#define BATCH 4
#define SEQ   2048
#define DMODEL 1024
#define DK    128
#define MTOT  (BATCH*SEQ)   // 8192
#define NEG_BIG (-1e30f)

// ---------------- scratch (device globals; no allocation allowed) -----------
// g_Q, g_K stored k-PERMUTED within 8-groups: pos(c) = (c&3)*2 + (c>>2)
// (fragment pairs {c, c+4} adjacent -> LDS.64/LDG.64 fragment loads).
// g_V, g_O normal layout.
__device__ float g_Q[MTOT * DK];
__device__ float g_K[MTOT * DK];
__device__ float g_V[MTOT * DK];
__device__ float g_O[MTOT * DK];

// split-KV partials: [B][32 q-tiles][4 chunks][64 rows][128 cols]
__device__ float g_pO[BATCH * 32 * 4 * 64 * 128];
__device__ float g_pm[BATCH * 32 * 4 * 64];
__device__ float g_pl[BATCH * 32 * 4 * 64];

// ---------------- tf32 helpers ------------------------------------------------
__device__ __forceinline__ unsigned f2tf(float x) {
    unsigned r;
    asm("cvt.rna.tf32.f32 %0, %1;" : "=r"(r) : "f"(x));
    return r;
}
__device__ __forceinline__ float f2tf_f(float x) { return __uint_as_float(f2tf(x)); }

// D = A(16x8, row) * B(8x8, col) + D, tf32 inputs, fp32 accum.
__device__ __forceinline__ void mma8(float* c, const unsigned* a, unsigned b0, unsigned b1) {
    asm volatile(
        "mma.sync.aligned.m16n8k8.row.col.f32.tf32.tf32.f32 "
        "{%0,%1,%2,%3},{%4,%5,%6,%7},{%8,%9},{%0,%1,%2,%3};"
        : "+f"(c[0]), "+f"(c[1]), "+f"(c[2]), "+f"(c[3])
        : "r"(a[0]), "r"(a[1]), "r"(a[2]), "r"(a[3]), "r"(b0), "r"(b1));
}

// ---------------- tf32 MMA GEMM body ------------------------------------------
// C[M,N] = A[M,K]*B[K,N] row-major. BM=128, BN=128, BK=16, 256 threads (8 warps).
// Warp grid 4(m) x 2(n); warp tile m32 x n64 (B-frags reused across 2 m16 halves).
// As stored k-PERMUTED (A_LD=24): A-frags are single LDS.64 per row.
#define G_BM 128
#define G_BN 128
#define G_BK 16
#define A_LD 24
#define B_LD 136

#define EPI_PLAIN     0   // fp32, normal layout (final output)
#define EPI_TF32_PERM 1   // tf32-rounded, column-permuted (g_Q, g_K)
#define EPI_TF32      2   // tf32-rounded, normal (g_V)

__device__ __forceinline__ void mma_gemm(
    const float* __restrict__ A, const float* __restrict__ B, float* __restrict__ C,
    int N, int K, int m0, int n0, int epi,
    float (*As)[G_BM][A_LD], float (*Bs)[G_BK][B_LD])
{
    const int tid  = threadIdx.x;
    const int lane = tid & 31, wid = tid >> 5;
    const int gid  = lane >> 2, tg = lane & 3;
    const int wm   = (wid & 3) * 32;
    const int wn   = (wid >> 2) * 64;

    const int ar = tid >> 2, ac = (tid & 3) << 2;        // A tile: rows ar, ar+64
    const int g8 = ac & 8, half = (ac >> 2) & 1;         // permute helpers
    const int br = tid >> 5, bc = (tid & 31) << 2;       // B tile: 16x128

    const float* Ap0 = A + (size_t)(m0 + ar) * K + ac;
    const float* Ap1 = A + (size_t)(m0 + ar + 64) * K + ac;
    const float* Bp0 = B + (size_t)br * N + n0 + bc;
    const float* Bp1 = B + (size_t)(br + 8) * N + n0 + bc;

    float acc[2][8][4];
#pragma unroll
    for (int h = 0; h < 2; ++h)
#pragma unroll
        for (int nb = 0; nb < 8; ++nb)
#pragma unroll
            for (int j = 0; j < 4; ++j) acc[h][nb][j] = 0.f;

    // preload tile 0 (A stored permuted into smem)
    {
        float4 a0 = *(const float4*)Ap0;
        float4 a1 = *(const float4*)Ap1;
        float4 b0 = *(const float4*)Bp0;
        float4 b1 = *(const float4*)Bp1;
        As[0][ar][g8 + half + 0]      = f2tf_f(a0.x);
        As[0][ar][g8 + half + 2]      = f2tf_f(a0.y);
        As[0][ar][g8 + half + 4]      = f2tf_f(a0.z);
        As[0][ar][g8 + half + 6]      = f2tf_f(a0.w);
        As[0][ar + 64][g8 + half + 0] = f2tf_f(a1.x);
        As[0][ar + 64][g8 + half + 2] = f2tf_f(a1.y);
        As[0][ar + 64][g8 + half + 4] = f2tf_f(a1.z);
        As[0][ar + 64][g8 + half + 6] = f2tf_f(a1.w);
        Bs[0][br][bc+0]   = f2tf_f(b0.x); Bs[0][br][bc+1]   = f2tf_f(b0.y);
        Bs[0][br][bc+2]   = f2tf_f(b0.z); Bs[0][br][bc+3]   = f2tf_f(b0.w);
        Bs[0][br+8][bc+0] = f2tf_f(b1.x); Bs[0][br+8][bc+1] = f2tf_f(b1.y);
        Bs[0][br+8][bc+2] = f2tf_f(b1.z); Bs[0][br+8][bc+3] = f2tf_f(b1.w);
    }
    __syncthreads();

    const int nk = K / G_BK;
    for (int it = 0; it < nk; ++it) {
        const int buf = it & 1;
        const bool hn = (it + 1 < nk);
        float4 an0, an1, bn0, bn1;
        if (hn) {
            an0 = *(const float4*)(Ap0 + (it + 1) * G_BK);
            an1 = *(const float4*)(Ap1 + (it + 1) * G_BK);
            bn0 = *(const float4*)(Bp0 + (size_t)(it + 1) * G_BK * N);
            bn1 = *(const float4*)(Bp1 + (size_t)(it + 1) * G_BK * N);
        }
#pragma unroll
        for (int kc = 0; kc < 2; ++kc) {
            float2 f0 = *(float2*)&As[buf][wm + gid     ][kc*8 + 2*tg];
            float2 f1 = *(float2*)&As[buf][wm + gid +  8][kc*8 + 2*tg];
            float2 f2 = *(float2*)&As[buf][wm + gid + 16][kc*8 + 2*tg];
            float2 f3 = *(float2*)&As[buf][wm + gid + 24][kc*8 + 2*tg];
            unsigned aA[4] = { __float_as_uint(f0.x), __float_as_uint(f1.x),
                               __float_as_uint(f0.y), __float_as_uint(f1.y) };
            unsigned aB[4] = { __float_as_uint(f2.x), __float_as_uint(f3.x),
                               __float_as_uint(f2.y), __float_as_uint(f3.y) };
#pragma unroll
            for (int nb = 0; nb < 8; ++nb) {
                unsigned b0 = __float_as_uint(Bs[buf][kc*8 + tg    ][wn + nb*8 + gid]);
                unsigned b1 = __float_as_uint(Bs[buf][kc*8 + tg + 4][wn + nb*8 + gid]);
                mma8(acc[0][nb], aA, b0, b1);
                mma8(acc[1][nb], aB, b0, b1);
            }
        }
        if (hn) {
            const int nxt = buf ^ 1;
            As[nxt][ar][g8 + half + 0]      = f2tf_f(an0.x);
            As[nxt][ar][g8 + half + 2]      = f2tf_f(an0.y);
            As[nxt][ar][g8 + half + 4]      = f2tf_f(an0.z);
            As[nxt][ar][g8 + half + 6]      = f2tf_f(an0.w);
            As[nxt][ar + 64][g8 + half + 0] = f2tf_f(an1.x);
            As[nxt][ar + 64][g8 + half + 2] = f2tf_f(an1.y);
            As[nxt][ar + 64][g8 + half + 4] = f2tf_f(an1.z);
            As[nxt][ar + 64][g8 + half + 6] = f2tf_f(an1.w);
            Bs[nxt][br][bc+0]   = f2tf_f(bn0.x); Bs[nxt][br][bc+1]   = f2tf_f(bn0.y);
            Bs[nxt][br][bc+2]   = f2tf_f(bn0.z); Bs[nxt][br][bc+3]   = f2tf_f(bn0.w);
            Bs[nxt][br+8][bc+0] = f2tf_f(bn1.x); Bs[nxt][br+8][bc+1] = f2tf_f(bn1.y);
            Bs[nxt][br+8][bc+2] = f2tf_f(bn1.z); Bs[nxt][br+8][bc+3] = f2tf_f(bn1.w);
            __syncthreads();
        }
    }

    // epilogue: frag set h covers rows {wm+16h+gid, wm+16h+gid+8}, cols {wn+nb*8+2tg,+1}
#pragma unroll
    for (int h = 0; h < 2; ++h) {
        const int row = m0 + wm + 16*h + gid;
#pragma unroll
        for (int nb = 0; nb < 8; ++nb) {
            const int colbase = n0 + wn + nb*8;
            float* c = acc[h][nb];
            if (epi == EPI_TF32_PERM) {
                const int p0 = ((2*tg) & 3) * 2 + (tg >> 1);
                const int p1 = ((2*tg+1) & 3) * 2 + (tg >> 1);
                C[(size_t)row * N + colbase + p0]       = f2tf_f(c[0]);
                C[(size_t)row * N + colbase + p1]       = f2tf_f(c[1]);
                C[(size_t)(row + 8) * N + colbase + p0] = f2tf_f(c[2]);
                C[(size_t)(row + 8) * N + colbase + p1] = f2tf_f(c[3]);
            } else if (epi == EPI_TF32) {
                const int col = colbase + 2*tg;
                *(float2*)&C[(size_t)row * N + col]       = make_float2(f2tf_f(c[0]), f2tf_f(c[1]));
                *(float2*)&C[(size_t)(row + 8) * N + col] = make_float2(f2tf_f(c[2]), f2tf_f(c[3]));
            } else {
                const int col = colbase + 2*tg;
                *(float2*)&C[(size_t)row * N + col]       = make_float2(c[0], c[1]);
                *(float2*)&C[(size_t)(row + 8) * N + col] = make_float2(c[2], c[3]);
            }
        }
    }
}

// QKV projection: grid (1, M/128, 3). Q/K written permuted, V normal (tf32-rounded).
__global__ __launch_bounds__(256, 2) void qkv_gemm_kernel(
    const float* __restrict__ x,
    const float* __restrict__ Wq,
    const float* __restrict__ Wk,
    const float* __restrict__ Wv)
{
    __shared__ __align__(16) float As[2][G_BM][A_LD];
    __shared__ __align__(16) float Bs[2][G_BK][B_LD];
    const float* W; float* out; int epi;
    if (blockIdx.z == 0)      { W = Wq; out = g_Q; epi = EPI_TF32_PERM; }
    else if (blockIdx.z == 1) { W = Wk; out = g_K; epi = EPI_TF32_PERM; }
    else                      { W = Wv; out = g_V; epi = EPI_TF32; }
    mma_gemm(x, W, out, DK, DMODEL, blockIdx.y * G_BM, 0, epi, As, Bs);
}

// Output projection: grid (DMODEL/128, M/128). A = g_O, normal layout.
__global__ __launch_bounds__(256, 2) void out_gemm_kernel(
    const float* __restrict__ Wo, float* __restrict__ out)
{
    __shared__ __align__(16) float As[2][G_BM][A_LD];
    __shared__ __align__(16) float Bs[2][G_BK][B_LD];
    mma_gemm(g_O, Wo, out, DMODEL, DK, blockIdx.y * G_BM, blockIdx.x * G_BN,
             EPI_PLAIN, As, Bs);
}

// ---------------- flash attention phase 1: split-KV, tf32 mma -----------------
// (unchanged from R11: BQ=64, BKV=64, 128 threads, Q frags via LDG.64 from
// permuted g_Q, K permuted -> LDS.64 B-frags, V normal, 80 blocks/batch)
#define K_LD 136
#define PS_LD 72
#define ATT_SMEM ((2 * 64 * K_LD + 64 * PS_LD) * sizeof(float))

__global__ __launch_bounds__(128) void attn_partial_kernel()
{
    extern __shared__ float sm[];
    float* Ks = sm;                   // 64 x 136 (permuted k, straight copy of g_K)
    float* Vs = Ks + 64 * K_LD;       // 64 x 136 (normal)
    float* Ps = Vs + 64 * K_LD;       // 64 x 72

    const int tid  = threadIdx.x;
    const int lane = tid & 31, wid = tid >> 5;
    const int gid  = lane >> 2, tg = lane & 3;
    const int b    = blockIdx.y;

    int qi, ch;
    {
        const int i = blockIdx.x;
        if (i < 8)       { qi = i;               ch = 0; }
        else if (i < 24) { int j = i - 8;  qi = 8  + (j >> 1); ch = j & 1; }
        else if (i < 48) { int j = i - 24; qi = 16 + j / 3;    ch = j - (j / 3) * 3; }
        else             { int j = i - 48; qi = 24 + (j >> 2); ch = j & 3; }
    }
    const int q0 = qi * 64;
    const int kt_begin = ch * 8;
    const int kt_end   = min(kt_begin + 8, qi + 1);

    const float* Qg = g_Q + (size_t)b * SEQ * DK;
    const float* Kg = g_K + (size_t)b * SEQ * DK;
    const float* Vg = g_V + (size_t)b * SEQ * DK;

    const int r0 = wid * 16 + gid;

    unsigned qa[16][4];
#pragma unroll
    for (int kc = 0; kc < 16; ++kc) {
        float2 q0f = *(const float2*)&Qg[(size_t)(q0 + r0    ) * DK + kc*8 + 2*tg];
        float2 q1f = *(const float2*)&Qg[(size_t)(q0 + r0 + 8) * DK + kc*8 + 2*tg];
        qa[kc][0] = __float_as_uint(q0f.x);
        qa[kc][1] = __float_as_uint(q1f.x);
        qa[kc][2] = __float_as_uint(q0f.y);
        qa[kc][3] = __float_as_uint(q1f.y);
    }

    float ob[16][4];
#pragma unroll
    for (int nb = 0; nb < 16; ++nb)
#pragma unroll
        for (int j = 0; j < 4; ++j) ob[nb][j] = 0.f;
    float m[2] = {NEG_BIG, NEG_BIG}, l[2] = {0.f, 0.f};
    const float scale = 0.08838834764831845f;

    for (int kt = kt_begin; kt < kt_end; ++kt) {
        const int k0 = kt * 64;
        const bool diag = (kt == qi);

        if (kt > kt_begin) __syncthreads();
#pragma unroll
        for (int t = 0; t < 16; ++t) {
            int e = t * 128 + tid;
            int row = e >> 5, c4 = (e & 31) << 2;
            *(float4*)&Ks[row * K_LD + c4] = *(const float4*)&Kg[(size_t)(k0 + row) * DK + c4];
            *(float4*)&Vs[row * K_LD + c4] = *(const float4*)&Vg[(size_t)(k0 + row) * DK + c4];
        }
        __syncthreads();

        float sc[8][4];
#pragma unroll
        for (int nb = 0; nb < 8; ++nb)
#pragma unroll
            for (int j = 0; j < 4; ++j) sc[nb][j] = 0.f;

#pragma unroll
        for (int kc = 0; kc < 16; ++kc) {
#pragma unroll
            for (int nb = 0; nb < 8; ++nb) {
                float2 bf = *(float2*)&Ks[(nb*8 + gid) * K_LD + kc*8 + 2*tg];
                mma8(sc[nb], qa[kc], __float_as_uint(bf.x), __float_as_uint(bf.y));
            }
        }

#pragma unroll
        for (int r = 0; r < 2; ++r) {
            const int qg = q0 + r0 + r*8;
            float mx = NEG_BIG;
#pragma unroll
            for (int nb = 0; nb < 8; ++nb) {
#pragma unroll
                for (int j = 0; j < 2; ++j) {
                    float v = sc[nb][2*r + j] * scale;
                    if (diag) {
                        const int kg = k0 + nb*8 + 2*tg + j;
                        if (kg > qg) v = NEG_BIG;
                    }
                    sc[nb][2*r + j] = v;
                    mx = fmaxf(mx, v);
                }
            }
            mx = fmaxf(mx, __shfl_xor_sync(0xffffffffu, mx, 1));
            mx = fmaxf(mx, __shfl_xor_sync(0xffffffffu, mx, 2));
            const float mnew  = fmaxf(m[r], mx);
            const float alpha = __expf(m[r] - mnew);
            float sum = 0.f;
#pragma unroll
            for (int nb = 0; nb < 8; ++nb) {
                float p0 = __expf(sc[nb][2*r    ] - mnew);
                float p1 = __expf(sc[nb][2*r + 1] - mnew);
                sum += p0 + p1;
                *(float2*)&Ps[(r0 + r*8) * PS_LD + nb*8 + 2*tg] = make_float2(f2tf_f(p0), f2tf_f(p1));
            }
            sum += __shfl_xor_sync(0xffffffffu, sum, 1);
            sum += __shfl_xor_sync(0xffffffffu, sum, 2);
            l[r] = l[r] * alpha + sum;
            m[r] = mnew;
#pragma unroll
            for (int nb = 0; nb < 16; ++nb) {
                ob[nb][2*r    ] *= alpha;
                ob[nb][2*r + 1] *= alpha;
            }
        }
        __syncwarp();

#pragma unroll
        for (int kc = 0; kc < 8; ++kc) {
            unsigned pa[4];
            pa[0] = __float_as_uint(Ps[(r0    ) * PS_LD + kc*8 + tg    ]);
            pa[1] = __float_as_uint(Ps[(r0 + 8) * PS_LD + kc*8 + tg    ]);
            pa[2] = __float_as_uint(Ps[(r0    ) * PS_LD + kc*8 + tg + 4]);
            pa[3] = __float_as_uint(Ps[(r0 + 8) * PS_LD + kc*8 + tg + 4]);
#pragma unroll
            for (int nb = 0; nb < 16; ++nb) {
                unsigned b0 = __float_as_uint(Vs[(kc*8 + tg    ) * K_LD + nb*8 + gid]);
                unsigned b1 = __float_as_uint(Vs[(kc*8 + tg + 4) * K_LD + nb*8 + gid]);
                mma8(ob[nb], pa, b0, b1);
            }
        }
    }

    const int slot = (b * 32 + qi) * 4 + ch;
    float* pO = g_pO + (size_t)slot * (64 * 128);
#pragma unroll
    for (int nb = 0; nb < 16; ++nb) {
        const int col = nb*8 + 2*tg;
        *(float2*)&pO[(size_t)(r0    ) * 128 + col] = make_float2(ob[nb][0], ob[nb][1]);
        *(float2*)&pO[(size_t)(r0 + 8) * 128 + col] = make_float2(ob[nb][2], ob[nb][3]);
    }
    if (tg == 0) {
        g_pm[slot * 64 + r0]     = m[0];
        g_pl[slot * 64 + r0]     = l[0];
        g_pm[slot * 64 + r0 + 8] = m[1];
        g_pl[slot * 64 + r0 + 8] = l[1];
    }
}

// ---------------- flash attention phase 2: merge partials ---------------------
__global__ __launch_bounds__(256) void attn_merge_kernel()
{
    const int qi = blockIdx.x;
    const int b  = blockIdx.y;
    const int nc = (qi >> 3) + 1;
    const int tid = threadIdx.x;
    const int r  = tid >> 2;
    const int cg = (tid & 3) << 5;
    const int base = (b * 32 + qi) * 4;

    float mc[4], wc[4];
    float mstar = NEG_BIG;
    for (int c = 0; c < nc; ++c) {
        mc[c] = g_pm[(base + c) * 64 + r];
        mstar = fmaxf(mstar, mc[c]);
    }
    float L = 0.f;
    for (int c = 0; c < nc; ++c) {
        wc[c] = __expf(mc[c] - mstar);
        L += wc[c] * g_pl[(base + c) * 64 + r];
    }
    const float inv = 1.f / L;

    float acc[32];
#pragma unroll
    for (int j = 0; j < 32; ++j) acc[j] = 0.f;

    for (int c = 0; c < nc; ++c) {
        const float w = wc[c];
        const float* src = g_pO + (size_t)(base + c) * (64 * 128) + (size_t)r * 128 + cg;
#pragma unroll
        for (int v = 0; v < 8; ++v) {
            float4 t = *(const float4*)&src[v * 4];
            acc[v*4+0] = fmaf(w, t.x, acc[v*4+0]);
            acc[v*4+1] = fmaf(w, t.y, acc[v*4+1]);
            acc[v*4+2] = fmaf(w, t.z, acc[v*4+2]);
            acc[v*4+3] = fmaf(w, t.w, acc[v*4+3]);
        }
    }

    float* dst = g_O + (size_t)b * SEQ * DK + (size_t)(qi * 64 + r) * 128 + cg;
#pragma unroll
    for (int v = 0; v < 8; ++v) {
        float4 t = make_float4(acc[v*4+0]*inv, acc[v*4+1]*inv, acc[v*4+2]*inv, acc[v*4+3]*inv);
        *(float4*)&dst[v * 4] = t;
    }
}

// ---------------- launch ------------------------------------------------------
extern "C" void kernel_launch(void* const* d_in, const int* in_sizes, int n_in,
                              void* d_out, int out_size)
{
    const float* x  = (const float*)d_in[0];
    const float* Wq = (const float*)d_in[1];
    const float* Wk = (const float*)d_in[2];
    const float* Wv = (const float*)d_in[3];
    const float* Wo = (const float*)d_in[4];
    float* out = (float*)d_out;

    cudaFuncSetAttribute(attn_partial_kernel,
                         cudaFuncAttributeMaxDynamicSharedMemorySize, (int)ATT_SMEM);

    // 1) QKV projections (tf32 mma): M=8192, N=128, K=1024; BM=128
    {
        dim3 grid(1, MTOT / G_BM, 3);
        qkv_gemm_kernel<<<grid, 256>>>(x, Wq, Wk, Wv);
    }
    // 2a) causal flash attention, split-KV partials (80 blocks/batch)
    {
        dim3 grid(80, BATCH);
        attn_partial_kernel<<<grid, 128, ATT_SMEM>>>();
    }
    // 2b) merge partials
    {
        dim3 grid(32, BATCH);
        attn_merge_kernel<<<grid, 256>>>();
    }
    // 3) output projection (tf32 mma): M=8192, N=1024, K=128; BM=128
    {
        dim3 grid(DMODEL / G_BN, MTOT / G_BM);
        out_gemm_kernel<<<grid, 256>>>(Wo, out);
    }
}